// round 15
// baseline (speedup 1.0000x reference)
#include <cuda_runtime.h>
#include <cstdint>
#include <math.h>

#define NSRC   8192
#define NLTN   64
#define NCTX   8256
#define BT     8
#define DIM    768
#define DEMB   512
#define HEADS  8
#define DHEAD  64
#define NTOK   (BT*NCTX)      // 66048
#define NSPLIT 43
#define SPLEN  192            // NCTX / NSPLIT (exact)
#define NCH    6              // SPLEN / 32 (exact)
#define BTH    (BT*HEADS)     // 64

// ------------------------- device scratch (no allocs allowed) ---------------
__device__ float d_ctxn[(size_t)NTOK*DIM];       // LayerNorm'd ctx (tf32-rounded)
__device__ float d_ltnn[BT*NLTN*DIM];            // compact ltn_n (full fp32)
__device__ float d_q   [BT*NLTN*DEMB];
__device__ float d_kv  [(size_t)NTOK*2*DEMB];    // k | v (tf32-rounded values)
__device__ float d_wt  [1024*DIM];               // Wkv^T, tf32-rounded
__device__ float d_po  [(size_t)NSPLIT*BTH*NLTN*DHEAD];
__device__ float d_pm  [NSPLIT*BTH*NLTN];
__device__ float d_pl  [NSPLIT*BTH*NLTN];

__device__ __forceinline__ unsigned f2tf(float x){
    unsigned r; asm("cvt.rna.tf32.f32 %0, %1;" : "=r"(r) : "f"(x)); return r;
}
__device__ __forceinline__ float tff(float x){ return __uint_as_float(f2tf(x)); }

__device__ __forceinline__ void mma_tf32(float* c, const unsigned* a, const unsigned* b){
    asm volatile(
        "mma.sync.aligned.m16n8k8.row.col.f32.tf32.tf32.f32 "
        "{%0,%1,%2,%3},{%4,%5,%6,%7},{%8,%9},{%0,%1,%2,%3};\n"
        : "+f"(c[0]), "+f"(c[1]), "+f"(c[2]), "+f"(c[3])
        : "r"(a[0]), "r"(a[1]), "r"(a[2]), "r"(a[3]), "r"(b[0]), "r"(b[1]));
}

__device__ __forceinline__ uint32_t smem_u32(const void* p){
    uint32_t a;
    asm("{ .reg .u64 t; cvta.to.shared.u64 t, %1; cvt.u32.u64 %0, t; }" : "=r"(a) : "l"(p));
    return a;
}

#define CP_ASYNC16(dst_u32, src_ptr) \
    asm volatile("cp.async.ca.shared.global [%0], [%1], 16;" :: "r"(dst_u32), "l"(src_ptr) : "memory")
#define CP_COMMIT() asm volatile("cp.async.commit_group;" ::: "memory")
#define CP_WAIT(N)  asm volatile("cp.async.wait_group %0;" :: "n"(N) : "memory")

// ------------------------- LayerNorm (+ fused Wkv transpose) ----------------
__global__ __launch_bounds__(256) void ln_kernel(
    const float* __restrict__ src, const float* __restrict__ ltn,
    const float* __restrict__ gs,  const float* __restrict__ bs,
    const float* __restrict__ gl,  const float* __restrict__ bl,
    const float* __restrict__ W)
{
    if (blockIdx.x >= NTOK/8){
        __shared__ float tile[32][33];
        int b2 = blockIdx.x - NTOK/8;
        int bx = (b2 & 31)*32;            // n base (0..1023)
        int by = (b2 >> 5)*32;            // k base (0..767)
        int x = threadIdx.x & 31, y = threadIdx.x >> 5;
        #pragma unroll
        for (int i = 0; i < 32; i += 8)
            tile[y+i][x] = W[(size_t)(by+y+i)*1024 + bx + x];
        __syncthreads();
        #pragma unroll
        for (int i = 0; i < 32; i += 8)
            d_wt[(size_t)(bx+y+i)*DIM + by + x] = tff(tile[x][y+i]);
        return;
    }

    int warp = blockIdx.x*8 + (threadIdx.x>>5);
    int lane = threadIdx.x & 31;
    int bt = warp / NCTX;
    int j  = warp % NCTX;
    const float *x, *g, *b;
    bool is_ltn = (j >= NSRC);
    if (!is_ltn){ x = src + (size_t)(bt*NSRC + j)*DIM;        g = gs; b = bs; }
    else        { x = ltn + (size_t)(bt*NLTN + (j-NSRC))*DIM; g = gl; b = bl; }

    float4 v[6];
    float s = 0.f, sq = 0.f;
    #pragma unroll
    for (int i = 0; i < 6; i++){
        v[i] = *(const float4*)(x + i*128 + lane*4);
        s  += v[i].x + v[i].y + v[i].z + v[i].w;
        sq += v[i].x*v[i].x + v[i].y*v[i].y + v[i].z*v[i].z + v[i].w*v[i].w;
    }
    #pragma unroll
    for (int o = 16; o > 0; o >>= 1){
        s  += __shfl_xor_sync(0xffffffffu, s,  o);
        sq += __shfl_xor_sync(0xffffffffu, sq, o);
    }
    float mu  = s * (1.f/DIM);
    float var = sq * (1.f/DIM) - mu*mu;
    float rs  = rsqrtf(var + 1e-5f);

    float* out  = d_ctxn + (size_t)warp*DIM;
    float* out2 = is_ltn ? (d_ltnn + (size_t)(bt*NLTN + (j-NSRC))*DIM) : 0;
    #pragma unroll
    for (int i = 0; i < 6; i++){
        int idx = i*128 + lane*4;
        float4 gv = *(const float4*)(g + idx);
        float4 bv = *(const float4*)(b + idx);
        float4 o4;
        o4.x = (v[i].x - mu)*rs*gv.x + bv.x;
        o4.y = (v[i].y - mu)*rs*gv.y + bv.y;
        o4.z = (v[i].z - mu)*rs*gv.z + bv.z;
        o4.w = (v[i].w - mu)*rs*gv.w + bv.w;
        if (is_ltn) *(float4*)(out2 + idx) = o4;     // full fp32 for Q path
        float4 r4;                                    // tf32-rounded for kv GEMM
        r4.x = tff(o4.x); r4.y = tff(o4.y); r4.z = tff(o4.z); r4.w = tff(o4.w);
        *(float4*)(out + idx) = r4;
    }
}

// ------------------------- generic small fp32 GEMM (64x64 tiles) ------------
__device__ __forceinline__ void gemm64_dyn(
    const float* __restrict__ A, const float* __restrict__ B, float* __restrict__ C,
    int N, int K, int m0, int n0, float* As /*16x68*/, float* Bs /*16x68*/)
{
    int t = threadIdx.x;
    int ar = t>>2, ak = (t&3)*4;
    int br = t>>4, bc = (t&15)*4;
    int ty = t>>4, tx = t&15;
    float acc[4][4];
    #pragma unroll
    for (int i=0;i<4;i++) for (int j=0;j<4;j++) acc[i][j]=0.f;

    for (int kc = 0; kc < K; kc += 16){
        float4 av = *(const float4*)(A + (size_t)(m0+ar)*K + kc + ak);
        float4 bv = *(const float4*)(B + (size_t)(kc+br)*N + n0 + bc);
        __syncthreads();
        As[(ak+0)*68+ar]=av.x; As[(ak+1)*68+ar]=av.y; As[(ak+2)*68+ar]=av.z; As[(ak+3)*68+ar]=av.w;
        Bs[br*68+bc+0]=bv.x; Bs[br*68+bc+1]=bv.y; Bs[br*68+bc+2]=bv.z; Bs[br*68+bc+3]=bv.w;
        __syncthreads();
        #pragma unroll
        for (int k = 0; k < 16; k++){
            float a[4], b[4];
            #pragma unroll
            for (int i=0;i<4;i++) a[i] = As[k*68 + ty*4+i];
            #pragma unroll
            for (int j=0;j<4;j++) b[j] = Bs[k*68 + tx*4+j];
            #pragma unroll
            for (int i=0;i<4;i++)
                #pragma unroll
                for (int j=0;j<4;j++) acc[i][j] += a[i]*b[j];
        }
    }
    #pragma unroll
    for (int i=0;i<4;i++)
        #pragma unroll
        for (int j=0;j<4;j++)
            C[(size_t)(m0+ty*4+i)*N + n0+tx*4+j] = acc[i][j];
}

// ------------------------- KV GEMM (+ fused Q projection) -------------------
#define KV_NCHUNK 24
#define KV_SMEM   73728
#define AOFF(b)   ((b)*18432)
#define BOFF(b)   (36864 + (b)*18432)

__global__ __launch_bounds__(256,2) void kv_gemm(const float* __restrict__ Wq)
{
    extern __shared__ float smf[];
    uint32_t sb = smem_u32(smf);

    if (blockIdx.y >= 516){
        gemm64_dyn(d_ltnn, Wq, d_q, DEMB, DIM,
                   (blockIdx.y - 516)*64, blockIdx.x*64, smf, smf + 1088);
        return;
    }

    int t = threadIdx.x, lane = t & 31, w = t >> 5;
    int m0 = blockIdx.y*128, n0 = blockIdx.x*128;
    int g = lane >> 2, tg = lane & 3;
    int wm = (w >> 2)*64, wn = (w & 3)*32;

    float acc[4][4][4];
    #pragma unroll
    for (int a=0;a<4;a++) for (int b=0;b<4;b++) for (int c=0;c<4;c++) acc[a][b][c]=0.f;

    const float* Ag = d_ctxn + (size_t)m0*DIM;
    const float* Bg = d_wt   + (size_t)n0*DIM;

    #pragma unroll
    for (int i = 0; i < 4; i++){
        int f = t + i*256, r = f>>3, cl = (f&7)*4;
        CP_ASYNC16(sb + AOFF(0) + (r*36+cl)*4, Ag + (size_t)r*DIM + cl);
        CP_ASYNC16(sb + BOFF(0) + (r*36+cl)*4, Bg + (size_t)r*DIM + cl);
    }
    CP_COMMIT();

    for (int c = 0; c < KV_NCHUNK; c++){
        if (c + 1 < KV_NCHUNK){
            int nb = (c+1) & 1, kc = (c+1)*32;
            #pragma unroll
            for (int i = 0; i < 4; i++){
                int f = t + i*256, r = f>>3, cl = (f&7)*4;
                CP_ASYNC16(sb + AOFF(nb) + (r*36+cl)*4, Ag + (size_t)r*DIM + kc + cl);
                CP_ASYNC16(sb + BOFF(nb) + (r*36+cl)*4, Bg + (size_t)r*DIM + kc + cl);
            }
            CP_COMMIT();
            CP_WAIT(1);
        } else {
            CP_WAIT(0);
        }
        __syncthreads();

        const float* As = smf + AOFF(c&1)/4;
        const float* Bs = smf + BOFF(c&1)/4;
        #pragma unroll
        for (int ks = 0; ks < 4; ks++){
            int k0 = ks*8;
            unsigned af[4][4], bf[4][2];
            #pragma unroll
            for (int mi = 0; mi < 4; mi++){
                int mb = wm + mi*16;
                af[mi][0] = __float_as_uint(As[(mb+g  )*36 + k0+tg  ]);
                af[mi][1] = __float_as_uint(As[(mb+8+g)*36 + k0+tg  ]);
                af[mi][2] = __float_as_uint(As[(mb+g  )*36 + k0+tg+4]);
                af[mi][3] = __float_as_uint(As[(mb+8+g)*36 + k0+tg+4]);
            }
            #pragma unroll
            for (int ni = 0; ni < 4; ni++){
                int nb2 = wn + ni*8;
                bf[ni][0] = __float_as_uint(Bs[(nb2+g)*36 + k0+tg  ]);
                bf[ni][1] = __float_as_uint(Bs[(nb2+g)*36 + k0+tg+4]);
            }
            #pragma unroll
            for (int mi = 0; mi < 4; mi++)
                #pragma unroll
                for (int ni = 0; ni < 4; ni++)
                    mma_tf32(acc[mi][ni], af[mi], bf[ni]);
        }
        __syncthreads();
    }

    #pragma unroll
    for (int mi = 0; mi < 4; mi++){
        #pragma unroll
        for (int ni = 0; ni < 4; ni++){
            int r0 = m0 + wm + mi*16 + g;
            int cc = n0 + wn + ni*8 + 2*tg;
            *(float2*)(d_kv + (size_t)r0*1024 + cc)     = make_float2(tff(acc[mi][ni][0]), tff(acc[mi][ni][1]));
            *(float2*)(d_kv + (size_t)(r0+8)*1024 + cc) = make_float2(tff(acc[mi][ni][2]), tff(acc[mi][ni][3]));
        }
    }
}

// ------------------------- Flash attention, split-KV, tf32 mma --------------
#define QS_O  0
#define KS_O  4352
#define VS_O  8704
#define SP_O  13312
#define ST_O  15616
#define ATT_SMEM 63232

__global__ __launch_bounds__(256) void attn_kernel()
{
    extern __shared__ float sm[];
    uint32_t sb = smem_u32(sm);
    unsigned* SPu = (unsigned*)(sm + SP_O);

    int split = blockIdx.x;
    int bth   = blockIdx.y;
    int bt = bth >> 3, h = bth & 7;
    int t = threadIdx.x, lane = t & 31, w = t >> 5;
    int g = lane >> 2, tg = lane & 3;

    {
        int i = t >> 2, dq = (t & 3)*16;
        const float* qp = d_q + (size_t)(bt*NLTN + i)*DEMB + h*DHEAD + dq;
        #pragma unroll
        for (int c = 0; c < 4; c++){
            float4 qv = *(const float4*)(qp + c*4);
            float4 r4;
            r4.x = tff(0.125f*qv.x); r4.y = tff(0.125f*qv.y);
            r4.z = tff(0.125f*qv.z); r4.w = tff(0.125f*qv.w);
            *(float4*)&sm[QS_O + i*68 + dq + c*4] = r4;
        }
    }
    if (t < 64){ sm[ST_O + t] = -1e30f; sm[ST_O + 64 + t] = 0.f; }

    int i0 = (w >> 1)*16;
    int j0 = (w & 1)*16;
    int d0 = (w & 1)*32;

    float oc[4][4];
    #pragma unroll
    for (int a=0;a<4;a++) for (int b=0;b<4;b++) oc[a][b]=0.f;

    int ldj = t & 31;
    int ldd = (t >> 5)*8;
    size_t tokbase = (size_t)(bt*NCTX + split*SPLEN);
    const float* kvbase = d_kv + (tokbase + ldj)*1024 + h*DHEAD + ldd;
    uint32_t Ksm = sb + (KS_O + ldj*68 + ldd)*4;
    uint32_t Vsm = sb + (VS_O + ldj*72 + ldd)*4;

    CP_ASYNC16(Ksm,      kvbase);
    CP_ASYNC16(Ksm + 16, kvbase + 4);
    CP_ASYNC16(Vsm,      kvbase + DEMB);
    CP_ASYNC16(Vsm + 16, kvbase + DEMB + 4);
    CP_COMMIT();

    for (int ch = 0; ch < NCH; ch++){
        int b = ch & 1;
        CP_WAIT(0);
        __syncthreads();                       // bar1: chunk ch ready; PV(ch-1) done

        if (ch + 1 < NCH){
            const float* kp = kvbase + (size_t)(ch+1)*32*1024;
            uint32_t Kd = Ksm + (b^1)*(2176*4);
            uint32_t Vd = Vsm + (b^1)*(2304*4);
            CP_ASYNC16(Kd,      kp);
            CP_ASYNC16(Kd + 16, kp + 4);
            CP_ASYNC16(Vd,      kp + DEMB);
            CP_ASYNC16(Vd + 16, kp + DEMB + 4);
            CP_COMMIT();
        }

        const float* Ksb = sm + KS_O + b*2176;
        const float* Vsb = sm + VS_O + b*2304;

        {
            float sc[2][4];
            #pragma unroll
            for (int ni=0;ni<2;ni++) for (int c=0;c<4;c++) sc[ni][c]=0.f;
            #pragma unroll
            for (int ks = 0; ks < 8; ks++){
                int k0 = ks*8;
                unsigned af[4], bf[2][2];
                af[0] = __float_as_uint(sm[QS_O + (i0+g  )*68 + k0+tg  ]);
                af[1] = __float_as_uint(sm[QS_O + (i0+8+g)*68 + k0+tg  ]);
                af[2] = __float_as_uint(sm[QS_O + (i0+g  )*68 + k0+tg+4]);
                af[3] = __float_as_uint(sm[QS_O + (i0+8+g)*68 + k0+tg+4]);
                #pragma unroll
                for (int ni = 0; ni < 2; ni++){
                    bf[ni][0] = __float_as_uint(Ksb[(j0+ni*8+g)*68 + k0+tg  ]);
                    bf[ni][1] = __float_as_uint(Ksb[(j0+ni*8+g)*68 + k0+tg+4]);
                }
                #pragma unroll
                for (int ni = 0; ni < 2; ni++) mma_tf32(sc[ni], af, bf[ni]);
            }
            #pragma unroll
            for (int ni = 0; ni < 2; ni++){
                int jc = j0 + ni*8 + 2*tg;
                SPu[(jc  )*72 + i0+g  ] = __float_as_uint(sc[ni][0]);
                SPu[(jc+1)*72 + i0+g  ] = __float_as_uint(sc[ni][1]);
                SPu[(jc  )*72 + i0+8+g] = __float_as_uint(sc[ni][2]);
                SPu[(jc+1)*72 + i0+8+g] = __float_as_uint(sc[ni][3]);
            }
        }
        __syncthreads();                       // bar2

        {
            int r  = w*8 + (lane>>2);
            int qt = lane & 3;
            float sv[8];
            float mx = -1e30f;
            #pragma unroll
            for (int c = 0; c < 8; c++){
                int j = qt + 4*c;
                float s = __uint_as_float(SPu[j*72 + r]);
                sv[c] = s;
                mx = fmaxf(mx, s);
            }
            mx = fmaxf(mx, __shfl_xor_sync(0xffffffffu, mx, 1));
            mx = fmaxf(mx, __shfl_xor_sync(0xffffffffu, mx, 2));
            float oldm = sm[ST_O + r];
            float newm = fmaxf(oldm, mx);
            float psum = 0.f;
            #pragma unroll
            for (int c = 0; c < 8; c++){
                float p = __expf(sv[c] - newm);
                psum += p;
                SPu[(qt + 4*c)*72 + r] = f2tf(p);
            }
            psum += __shfl_xor_sync(0xffffffffu, psum, 1);
            psum += __shfl_xor_sync(0xffffffffu, psum, 2);
            if (qt == 0){
                float f = __expf(oldm - newm);
                sm[ST_O + 64 + r] = sm[ST_O + 64 + r]*f + psum;
                sm[ST_O + r]       = newm;
                sm[ST_O + 128 + r] = f;
            }
        }
        __syncthreads();                       // bar3

        {
            float f1 = sm[ST_O + 128 + i0+g], f2 = sm[ST_O + 128 + i0+8+g];
            #pragma unroll
            for (int ni = 0; ni < 4; ni++){
                oc[ni][0]*=f1; oc[ni][1]*=f1; oc[ni][2]*=f2; oc[ni][3]*=f2;
            }
            #pragma unroll
            for (int ks = 0; ks < 4; ks++){
                int k0 = ks*8;
                unsigned af[4], bf[4][2];
                af[0] = SPu[(k0+tg  )*72 + i0+g  ];
                af[1] = SPu[(k0+tg  )*72 + i0+8+g];
                af[2] = SPu[(k0+tg+4)*72 + i0+g  ];
                af[3] = SPu[(k0+tg+4)*72 + i0+8+g];
                #pragma unroll
                for (int ni = 0; ni < 4; ni++){
                    bf[ni][0] = __float_as_uint(Vsb[(k0+tg  )*72 + d0+ni*8+g]);
                    bf[ni][1] = __float_as_uint(Vsb[(k0+tg+4)*72 + d0+ni*8+g]);
                }
                #pragma unroll
                for (int ni = 0; ni < 4; ni++) mma_tf32(oc[ni], af, bf[ni]);
            }
        }
    }

    __syncthreads();
    {
        float* po = d_po + (size_t)(split*BTH + bth)*NLTN*DHEAD;
        #pragma unroll
        for (int ni = 0; ni < 4; ni++){
            int cc = d0 + ni*8 + 2*tg;
            *(float2*)(po + (i0+g)*DHEAD + cc)   = make_float2(oc[ni][0], oc[ni][1]);
            *(float2*)(po + (i0+8+g)*DHEAD + cc) = make_float2(oc[ni][2], oc[ni][3]);
        }
        if (t < 64){
            d_pm[(split*BTH + bth)*NLTN + t] = sm[ST_O + t];
            d_pl[(split*BTH + bth)*NLTN + t] = sm[ST_O + 64 + t];
        }
    }
}

// ------------------------- fused combine + output projection ----------------
// 128 blocks x 4 rows. Phase 0: stats (M,L,w_s) per (row,head). Phase 1:
// weighted po accumulate -> normalized S[4][512] in smem. Phase 2: S @ Wo.
__global__ __launch_bounds__(256) void co_kernel(const float* __restrict__ Wo,
                                                 float* __restrict__ out)
{
    __shared__ float wsm[32][44];     // w_s per (row,head) pair
    __shared__ float winv[32];
    __shared__ float S[4][516];

    int t = threadIdx.x;

    // ---- phase 0: per (row, head) stats ----
    if (t < 32){
        int r = t >> 3, h = t & 7;
        int rg = blockIdx.x*4 + r;
        int bt = rg >> 6, i = rg & 63;
        int bth = bt*8 + h;
        float M = -1e30f;
        #pragma unroll 4
        for (int s = 0; s < NSPLIT; s++)
            M = fmaxf(M, d_pm[(s*BTH + bth)*NLTN + i]);
        float L = 0.f;
        #pragma unroll 4
        for (int s = 0; s < NSPLIT; s++){
            float ws = __expf(d_pm[(s*BTH + bth)*NLTN + i] - M);
            wsm[t][s] = ws;
            L += ws * d_pl[(s*BTH + bth)*NLTN + i];
        }
        winv[t] = 1.f / L;
    }
    __syncthreads();

    // ---- phase 1: combine po -> S ----
    {
        int r = t >> 6;                 // 0..3
        int c0 = (t & 63)*8;            // col base within 512
        int h = c0 >> 6;
        int p = r*8 + h;
        int rg = blockIdx.x*4 + r;
        int bt = rg >> 6, i = rg & 63;
        int bth = bt*8 + h;
        int dc = c0 & 63;
        float a[8];
        #pragma unroll
        for (int j = 0; j < 8; j++) a[j] = 0.f;
        for (int s = 0; s < NSPLIT; s++){
            float ws = wsm[p][s];
            const float* pp = d_po + ((size_t)(s*BTH + bth)*NLTN + i)*DHEAD + dc;
            float4 v0 = *(const float4*)pp;
            float4 v1 = *(const float4*)(pp + 4);
            a[0] += ws*v0.x; a[1] += ws*v0.y; a[2] += ws*v0.z; a[3] += ws*v0.w;
            a[4] += ws*v1.x; a[5] += ws*v1.y; a[6] += ws*v1.z; a[7] += ws*v1.w;
        }
        float il = winv[p];
        float4 o0 = make_float4(a[0]*il, a[1]*il, a[2]*il, a[3]*il);
        float4 o1 = make_float4(a[4]*il, a[5]*il, a[6]*il, a[7]*il);
        *(float4*)&S[r][c0]     = o0;
        *(float4*)&S[r][c0 + 4] = o1;
    }
    __syncthreads();

    // ---- phase 2: out[4 rows][768] = S @ Wo ----
    {
        int c = t*3;                    // 3 cols per thread
        float acc[4][3];
        #pragma unroll
        for (int r = 0; r < 4; r++)
            #pragma unroll
            for (int j = 0; j < 3; j++) acc[r][j] = 0.f;

        for (int k4 = 0; k4 < DEMB; k4 += 4){
            float4 sv[4];
            #pragma unroll
            for (int r = 0; r < 4; r++) sv[r] = *(const float4*)&S[r][k4];
            #pragma unroll
            for (int kk = 0; kk < 4; kk++){
                const float* wp = Wo + (size_t)(k4+kk)*DIM + c;
                float w0 = wp[0], w1 = wp[1], w2 = wp[2];
                #pragma unroll
                for (int r = 0; r < 4; r++){
                    float s = (kk==0)?sv[r].x:(kk==1)?sv[r].y:(kk==2)?sv[r].z:sv[r].w;
                    acc[r][0] += s*w0; acc[r][1] += s*w1; acc[r][2] += s*w2;
                }
            }
        }
        #pragma unroll
        for (int r = 0; r < 4; r++){
            int rg = blockIdx.x*4 + r;
            float* op = out + (size_t)rg*DIM + c;
            op[0] = acc[r][0]; op[1] = acc[r][1]; op[2] = acc[r][2];
        }
    }
}

// ------------------------- launch -------------------------------------------
extern "C" void kernel_launch(void* const* d_in, const int* in_sizes, int n_in,
                              void* d_out, int out_size)
{
    const float* src = (const float*)d_in[0];
    const float* ltn = (const float*)d_in[1];
    const float* gs  = (const float*)d_in[2];
    const float* bs  = (const float*)d_in[3];
    const float* gl  = (const float*)d_in[4];
    const float* bl  = (const float*)d_in[5];
    const float* Wq  = (const float*)d_in[6];
    const float* Wkv = (const float*)d_in[7];
    const float* Wo  = (const float*)d_in[8];
    float* out = (float*)d_out;

    cudaFuncSetAttribute(kv_gemm,     cudaFuncAttributeMaxDynamicSharedMemorySize, KV_SMEM);
    cudaFuncSetAttribute(attn_kernel, cudaFuncAttributeMaxDynamicSharedMemorySize, ATT_SMEM);

    ln_kernel<<<NTOK/8 + 768, 256>>>(src, ltn, gs, bs, gl, bl, Wkv);
    kv_gemm<<<dim3(8, 524), 256, KV_SMEM>>>(Wq);
    attn_kernel<<<dim3(NSPLIT, BTH), 256, ATT_SMEM>>>();
    co_kernel<<<128, 256>>>(Wo, out);
}

// round 16
// speedup vs baseline: 1.0987x; 1.0987x over previous
#include <cuda_runtime.h>
#include <cstdint>
#include <math.h>

#define NSRC   8192
#define NLTN   64
#define NCTX   8256
#define BT     8
#define DIM    768
#define DEMB   512
#define HEADS  8
#define DHEAD  64
#define NTOK   (BT*NCTX)      // 66048
#define NSPLIT 43
#define SPLEN  192            // NCTX / NSPLIT (exact)
#define NCH    6              // SPLEN / 32 (exact)
#define BTH    (BT*HEADS)     // 64

// ------------------------- device scratch (no allocs allowed) ---------------
__device__ float d_ctxn[(size_t)NTOK*DIM];       // LayerNorm'd ctx (tf32-rounded)
__device__ float d_ltnn[BT*NLTN*DIM];            // compact ltn_n (full fp32)
__device__ float d_q   [BT*NLTN*DEMB];
__device__ float d_kv  [(size_t)NTOK*2*DEMB];    // k | v (tf32-rounded values)
__device__ float d_wt  [1024*DIM];               // Wkv^T, tf32-rounded
__device__ float d_po  [(size_t)NSPLIT*BTH*NLTN*DHEAD];
__device__ float d_pm  [NSPLIT*BTH*NLTN];
__device__ float d_pl  [NSPLIT*BTH*NLTN];
__device__ float d_obuf[BT*NLTN*DEMB];

__device__ __forceinline__ unsigned f2tf(float x){
    unsigned r; asm("cvt.rna.tf32.f32 %0, %1;" : "=r"(r) : "f"(x)); return r;
}
__device__ __forceinline__ float tff(float x){ return __uint_as_float(f2tf(x)); }

__device__ __forceinline__ void mma_tf32(float* c, const unsigned* a, const unsigned* b){
    asm volatile(
        "mma.sync.aligned.m16n8k8.row.col.f32.tf32.tf32.f32 "
        "{%0,%1,%2,%3},{%4,%5,%6,%7},{%8,%9},{%0,%1,%2,%3};\n"
        : "+f"(c[0]), "+f"(c[1]), "+f"(c[2]), "+f"(c[3])
        : "r"(a[0]), "r"(a[1]), "r"(a[2]), "r"(a[3]), "r"(b[0]), "r"(b[1]));
}

__device__ __forceinline__ uint32_t smem_u32(const void* p){
    uint32_t a;
    asm("{ .reg .u64 t; cvta.to.shared.u64 t, %1; cvt.u32.u64 %0, t; }" : "=r"(a) : "l"(p));
    return a;
}

#define CP_ASYNC16(dst_u32, src_ptr) \
    asm volatile("cp.async.ca.shared.global [%0], [%1], 16;" :: "r"(dst_u32), "l"(src_ptr) : "memory")
#define CP_COMMIT() asm volatile("cp.async.commit_group;" ::: "memory")
#define CP_WAIT(N)  asm volatile("cp.async.wait_group %0;" :: "n"(N) : "memory")

// ------------------------- LayerNorm (+ fused Wkv transpose) ----------------
__global__ __launch_bounds__(256) void ln_kernel(
    const float* __restrict__ src, const float* __restrict__ ltn,
    const float* __restrict__ gs,  const float* __restrict__ bs,
    const float* __restrict__ gl,  const float* __restrict__ bl,
    const float* __restrict__ W)
{
    if (blockIdx.x >= NTOK/8){
        __shared__ float tile[32][33];
        int b2 = blockIdx.x - NTOK/8;
        int bx = (b2 & 31)*32;            // n base (0..1023)
        int by = (b2 >> 5)*32;            // k base (0..767)
        int x = threadIdx.x & 31, y = threadIdx.x >> 5;
        #pragma unroll
        for (int i = 0; i < 32; i += 8)
            tile[y+i][x] = W[(size_t)(by+y+i)*1024 + bx + x];
        __syncthreads();
        #pragma unroll
        for (int i = 0; i < 32; i += 8)
            d_wt[(size_t)(bx+y+i)*DIM + by + x] = tff(tile[x][y+i]);
        return;
    }

    int warp = blockIdx.x*8 + (threadIdx.x>>5);
    int lane = threadIdx.x & 31;
    int bt = warp / NCTX;
    int j  = warp % NCTX;
    const float *x, *g, *b;
    bool is_ltn = (j >= NSRC);
    if (!is_ltn){ x = src + (size_t)(bt*NSRC + j)*DIM;        g = gs; b = bs; }
    else        { x = ltn + (size_t)(bt*NLTN + (j-NSRC))*DIM; g = gl; b = bl; }

    float4 v[6];
    float s = 0.f, sq = 0.f;
    #pragma unroll
    for (int i = 0; i < 6; i++){
        v[i] = *(const float4*)(x + i*128 + lane*4);
        s  += v[i].x + v[i].y + v[i].z + v[i].w;
        sq += v[i].x*v[i].x + v[i].y*v[i].y + v[i].z*v[i].z + v[i].w*v[i].w;
    }
    #pragma unroll
    for (int o = 16; o > 0; o >>= 1){
        s  += __shfl_xor_sync(0xffffffffu, s,  o);
        sq += __shfl_xor_sync(0xffffffffu, sq, o);
    }
    float mu  = s * (1.f/DIM);
    float var = sq * (1.f/DIM) - mu*mu;
    float rs  = rsqrtf(var + 1e-5f);

    float* out  = d_ctxn + (size_t)warp*DIM;
    float* out2 = is_ltn ? (d_ltnn + (size_t)(bt*NLTN + (j-NSRC))*DIM) : 0;
    #pragma unroll
    for (int i = 0; i < 6; i++){
        int idx = i*128 + lane*4;
        float4 gv = *(const float4*)(g + idx);
        float4 bv = *(const float4*)(b + idx);
        float4 o4;
        o4.x = (v[i].x - mu)*rs*gv.x + bv.x;
        o4.y = (v[i].y - mu)*rs*gv.y + bv.y;
        o4.z = (v[i].z - mu)*rs*gv.z + bv.z;
        o4.w = (v[i].w - mu)*rs*gv.w + bv.w;
        if (is_ltn) *(float4*)(out2 + idx) = o4;     // full fp32 for Q path
        float4 r4;                                    // tf32-rounded for kv GEMM
        r4.x = tff(o4.x); r4.y = tff(o4.y); r4.z = tff(o4.z); r4.w = tff(o4.w);
        *(float4*)(out + idx) = r4;
    }
}

// ------------------------- generic small fp32 GEMM (64x64 tiles) ------------
__device__ __forceinline__ void gemm64_dyn(
    const float* __restrict__ A, const float* __restrict__ B, float* __restrict__ C,
    int N, int K, int m0, int n0, float* As /*16x68*/, float* Bs /*16x68*/)
{
    int t = threadIdx.x;
    int ar = t>>2, ak = (t&3)*4;
    int br = t>>4, bc = (t&15)*4;
    int ty = t>>4, tx = t&15;
    float acc[4][4];
    #pragma unroll
    for (int i=0;i<4;i++) for (int j=0;j<4;j++) acc[i][j]=0.f;

    for (int kc = 0; kc < K; kc += 16){
        float4 av = *(const float4*)(A + (size_t)(m0+ar)*K + kc + ak);
        float4 bv = *(const float4*)(B + (size_t)(kc+br)*N + n0 + bc);
        __syncthreads();
        As[(ak+0)*68+ar]=av.x; As[(ak+1)*68+ar]=av.y; As[(ak+2)*68+ar]=av.z; As[(ak+3)*68+ar]=av.w;
        Bs[br*68+bc+0]=bv.x; Bs[br*68+bc+1]=bv.y; Bs[br*68+bc+2]=bv.z; Bs[br*68+bc+3]=bv.w;
        __syncthreads();
        #pragma unroll
        for (int k = 0; k < 16; k++){
            float a[4], b[4];
            #pragma unroll
            for (int i=0;i<4;i++) a[i] = As[k*68 + ty*4+i];
            #pragma unroll
            for (int j=0;j<4;j++) b[j] = Bs[k*68 + tx*4+j];
            #pragma unroll
            for (int i=0;i<4;i++)
                #pragma unroll
                for (int j=0;j<4;j++) acc[i][j] += a[i]*b[j];
        }
    }
    #pragma unroll
    for (int i=0;i<4;i++)
        #pragma unroll
        for (int j=0;j<4;j++)
            C[(size_t)(m0+ty*4+i)*N + n0+tx*4+j] = acc[i][j];
}

__global__ __launch_bounds__(256) void o_gemm(const float* __restrict__ Wo, float* __restrict__ out){
    __shared__ float As[16*68], Bs[16*68];
    gemm64_dyn(d_obuf, Wo, out, DIM, DEMB, blockIdx.y*64, blockIdx.x*64, As, Bs);
}

// ------------------------- KV GEMM (+ fused Q projection) -------------------
#define KV_NCHUNK 24
#define KV_SMEM   73728
#define AOFF(b)   ((b)*18432)
#define BOFF(b)   (36864 + (b)*18432)

__global__ __launch_bounds__(256,2) void kv_gemm(const float* __restrict__ Wq)
{
    extern __shared__ float smf[];
    uint32_t sb = smem_u32(smf);

    if (blockIdx.y >= 516){
        gemm64_dyn(d_ltnn, Wq, d_q, DEMB, DIM,
                   (blockIdx.y - 516)*64, blockIdx.x*64, smf, smf + 1088);
        return;
    }

    int t = threadIdx.x, lane = t & 31, w = t >> 5;
    int m0 = blockIdx.y*128, n0 = blockIdx.x*128;
    int g = lane >> 2, tg = lane & 3;
    int wm = (w >> 2)*64, wn = (w & 3)*32;

    float acc[4][4][4];
    #pragma unroll
    for (int a=0;a<4;a++) for (int b=0;b<4;b++) for (int c=0;c<4;c++) acc[a][b][c]=0.f;

    const float* Ag = d_ctxn + (size_t)m0*DIM;
    const float* Bg = d_wt   + (size_t)n0*DIM;

    #pragma unroll
    for (int i = 0; i < 4; i++){
        int f = t + i*256, r = f>>3, cl = (f&7)*4;
        CP_ASYNC16(sb + AOFF(0) + (r*36+cl)*4, Ag + (size_t)r*DIM + cl);
        CP_ASYNC16(sb + BOFF(0) + (r*36+cl)*4, Bg + (size_t)r*DIM + cl);
    }
    CP_COMMIT();

    for (int c = 0; c < KV_NCHUNK; c++){
        if (c + 1 < KV_NCHUNK){
            int nb = (c+1) & 1, kc = (c+1)*32;
            #pragma unroll
            for (int i = 0; i < 4; i++){
                int f = t + i*256, r = f>>3, cl = (f&7)*4;
                CP_ASYNC16(sb + AOFF(nb) + (r*36+cl)*4, Ag + (size_t)r*DIM + kc + cl);
                CP_ASYNC16(sb + BOFF(nb) + (r*36+cl)*4, Bg + (size_t)r*DIM + kc + cl);
            }
            CP_COMMIT();
            CP_WAIT(1);
        } else {
            CP_WAIT(0);
        }
        __syncthreads();

        const float* As = smf + AOFF(c&1)/4;
        const float* Bs = smf + BOFF(c&1)/4;
        #pragma unroll
        for (int ks = 0; ks < 4; ks++){
            int k0 = ks*8;
            unsigned af[4][4], bf[4][2];
            #pragma unroll
            for (int mi = 0; mi < 4; mi++){
                int mb = wm + mi*16;
                af[mi][0] = __float_as_uint(As[(mb+g  )*36 + k0+tg  ]);
                af[mi][1] = __float_as_uint(As[(mb+8+g)*36 + k0+tg  ]);
                af[mi][2] = __float_as_uint(As[(mb+g  )*36 + k0+tg+4]);
                af[mi][3] = __float_as_uint(As[(mb+8+g)*36 + k0+tg+4]);
            }
            #pragma unroll
            for (int ni = 0; ni < 4; ni++){
                int nb2 = wn + ni*8;
                bf[ni][0] = __float_as_uint(Bs[(nb2+g)*36 + k0+tg  ]);
                bf[ni][1] = __float_as_uint(Bs[(nb2+g)*36 + k0+tg+4]);
            }
            #pragma unroll
            for (int mi = 0; mi < 4; mi++)
                #pragma unroll
                for (int ni = 0; ni < 4; ni++)
                    mma_tf32(acc[mi][ni], af[mi], bf[ni]);
        }
        __syncthreads();
    }

    #pragma unroll
    for (int mi = 0; mi < 4; mi++){
        #pragma unroll
        for (int ni = 0; ni < 4; ni++){
            int r0 = m0 + wm + mi*16 + g;
            int cc = n0 + wn + ni*8 + 2*tg;
            *(float2*)(d_kv + (size_t)r0*1024 + cc)     = make_float2(tff(acc[mi][ni][0]), tff(acc[mi][ni][1]));
            *(float2*)(d_kv + (size_t)(r0+8)*1024 + cc) = make_float2(tff(acc[mi][ni][2]), tff(acc[mi][ni][3]));
        }
    }
}

// ------------------------- Flash attention, split-KV, tf32 mma --------------
#define QS_O  0
#define KS_O  4352
#define VS_O  8704
#define SP_O  13312
#define ST_O  15616
#define ATT_SMEM 63232

__global__ __launch_bounds__(256) void attn_kernel()
{
    extern __shared__ float sm[];
    uint32_t sb = smem_u32(sm);
    unsigned* SPu = (unsigned*)(sm + SP_O);

    int split = blockIdx.x;
    int bth   = blockIdx.y;
    int bt = bth >> 3, h = bth & 7;
    int t = threadIdx.x, lane = t & 31, w = t >> 5;
    int g = lane >> 2, tg = lane & 3;

    {
        int i = t >> 2, dq = (t & 3)*16;
        const float* qp = d_q + (size_t)(bt*NLTN + i)*DEMB + h*DHEAD + dq;
        #pragma unroll
        for (int c = 0; c < 4; c++){
            float4 qv = *(const float4*)(qp + c*4);
            float4 r4;
            r4.x = tff(0.125f*qv.x); r4.y = tff(0.125f*qv.y);
            r4.z = tff(0.125f*qv.z); r4.w = tff(0.125f*qv.w);
            *(float4*)&sm[QS_O + i*68 + dq + c*4] = r4;
        }
    }
    if (t < 64){ sm[ST_O + t] = -1e30f; sm[ST_O + 64 + t] = 0.f; }

    int i0 = (w >> 1)*16;
    int j0 = (w & 1)*16;
    int d0 = (w & 1)*32;

    float oc[4][4];
    #pragma unroll
    for (int a=0;a<4;a++) for (int b=0;b<4;b++) oc[a][b]=0.f;

    int ldj = t & 31;
    int ldd = (t >> 5)*8;
    size_t tokbase = (size_t)(bt*NCTX + split*SPLEN);
    const float* kvbase = d_kv + (tokbase + ldj)*1024 + h*DHEAD + ldd;
    uint32_t Ksm = sb + (KS_O + ldj*68 + ldd)*4;
    uint32_t Vsm = sb + (VS_O + ldj*72 + ldd)*4;

    CP_ASYNC16(Ksm,      kvbase);
    CP_ASYNC16(Ksm + 16, kvbase + 4);
    CP_ASYNC16(Vsm,      kvbase + DEMB);
    CP_ASYNC16(Vsm + 16, kvbase + DEMB + 4);
    CP_COMMIT();

    for (int ch = 0; ch < NCH; ch++){
        int b = ch & 1;
        CP_WAIT(0);
        __syncthreads();                       // bar1: chunk ch ready; PV(ch-1) done

        if (ch + 1 < NCH){
            const float* kp = kvbase + (size_t)(ch+1)*32*1024;
            uint32_t Kd = Ksm + (b^1)*(2176*4);
            uint32_t Vd = Vsm + (b^1)*(2304*4);
            CP_ASYNC16(Kd,      kp);
            CP_ASYNC16(Kd + 16, kp + 4);
            CP_ASYNC16(Vd,      kp + DEMB);
            CP_ASYNC16(Vd + 16, kp + DEMB + 4);
            CP_COMMIT();
        }

        const float* Ksb = sm + KS_O + b*2176;
        const float* Vsb = sm + VS_O + b*2304;

        {
            float sc[2][4];
            #pragma unroll
            for (int ni=0;ni<2;ni++) for (int c=0;c<4;c++) sc[ni][c]=0.f;
            #pragma unroll
            for (int ks = 0; ks < 8; ks++){
                int k0 = ks*8;
                unsigned af[4], bf[2][2];
                af[0] = __float_as_uint(sm[QS_O + (i0+g  )*68 + k0+tg  ]);
                af[1] = __float_as_uint(sm[QS_O + (i0+8+g)*68 + k0+tg  ]);
                af[2] = __float_as_uint(sm[QS_O + (i0+g  )*68 + k0+tg+4]);
                af[3] = __float_as_uint(sm[QS_O + (i0+8+g)*68 + k0+tg+4]);
                #pragma unroll
                for (int ni = 0; ni < 2; ni++){
                    bf[ni][0] = __float_as_uint(Ksb[(j0+ni*8+g)*68 + k0+tg  ]);
                    bf[ni][1] = __float_as_uint(Ksb[(j0+ni*8+g)*68 + k0+tg+4]);
                }
                #pragma unroll
                for (int ni = 0; ni < 2; ni++) mma_tf32(sc[ni], af, bf[ni]);
            }
            #pragma unroll
            for (int ni = 0; ni < 2; ni++){
                int jc = j0 + ni*8 + 2*tg;
                SPu[(jc  )*72 + i0+g  ] = __float_as_uint(sc[ni][0]);
                SPu[(jc+1)*72 + i0+g  ] = __float_as_uint(sc[ni][1]);
                SPu[(jc  )*72 + i0+8+g] = __float_as_uint(sc[ni][2]);
                SPu[(jc+1)*72 + i0+8+g] = __float_as_uint(sc[ni][3]);
            }
        }
        __syncthreads();                       // bar2

        {
            int r  = w*8 + (lane>>2);
            int qt = lane & 3;
            float sv[8];
            float mx = -1e30f;
            #pragma unroll
            for (int c = 0; c < 8; c++){
                int j = qt + 4*c;
                float s = __uint_as_float(SPu[j*72 + r]);
                sv[c] = s;
                mx = fmaxf(mx, s);
            }
            mx = fmaxf(mx, __shfl_xor_sync(0xffffffffu, mx, 1));
            mx = fmaxf(mx, __shfl_xor_sync(0xffffffffu, mx, 2));
            float oldm = sm[ST_O + r];
            float newm = fmaxf(oldm, mx);
            float psum = 0.f;
            #pragma unroll
            for (int c = 0; c < 8; c++){
                float p = __expf(sv[c] - newm);
                psum += p;
                SPu[(qt + 4*c)*72 + r] = f2tf(p);
            }
            psum += __shfl_xor_sync(0xffffffffu, psum, 1);
            psum += __shfl_xor_sync(0xffffffffu, psum, 2);
            if (qt == 0){
                float f = __expf(oldm - newm);
                sm[ST_O + 64 + r] = sm[ST_O + 64 + r]*f + psum;
                sm[ST_O + r]       = newm;
                sm[ST_O + 128 + r] = f;
            }
        }
        __syncthreads();                       // bar3

        {
            float f1 = sm[ST_O + 128 + i0+g], f2 = sm[ST_O + 128 + i0+8+g];
            #pragma unroll
            for (int ni = 0; ni < 4; ni++){
                oc[ni][0]*=f1; oc[ni][1]*=f1; oc[ni][2]*=f2; oc[ni][3]*=f2;
            }
            #pragma unroll
            for (int ks = 0; ks < 4; ks++){
                int k0 = ks*8;
                unsigned af[4], bf[4][2];
                af[0] = SPu[(k0+tg  )*72 + i0+g  ];
                af[1] = SPu[(k0+tg  )*72 + i0+8+g];
                af[2] = SPu[(k0+tg+4)*72 + i0+g  ];
                af[3] = SPu[(k0+tg+4)*72 + i0+8+g];
                #pragma unroll
                for (int ni = 0; ni < 4; ni++){
                    bf[ni][0] = __float_as_uint(Vsb[(k0+tg  )*72 + d0+ni*8+g]);
                    bf[ni][1] = __float_as_uint(Vsb[(k0+tg+4)*72 + d0+ni*8+g]);
                }
                #pragma unroll
                for (int ni = 0; ni < 4; ni++) mma_tf32(oc[ni], af, bf[ni]);
            }
        }
    }

    __syncthreads();
    {
        float* po = d_po + (size_t)(split*BTH + bth)*NLTN*DHEAD;
        #pragma unroll
        for (int ni = 0; ni < 4; ni++){
            int cc = d0 + ni*8 + 2*tg;
            *(float2*)(po + (i0+g)*DHEAD + cc)   = make_float2(oc[ni][0], oc[ni][1]);
            *(float2*)(po + (i0+8+g)*DHEAD + cc) = make_float2(oc[ni][2], oc[ni][3]);
        }
        if (t < 64){
            d_pm[(split*BTH + bth)*NLTN + t] = sm[ST_O + t];
            d_pl[(split*BTH + bth)*NLTN + t] = sm[ST_O + 64 + t];
        }
    }
}

// ------------------------- combine splits (1 warp = 1 pair-half) ------------
__global__ __launch_bounds__(256) void combine_kernel()
{
    int gw2 = blockIdx.x*8 + (threadIdx.x>>5);  // 0..8191
    int lane = threadIdx.x & 31;
    int pair = gw2 >> 1;                        // 0..4095 : (bth, i)
    int half = gw2 & 1;                         // 0/1 : d-half
    int bth = pair >> 6, i = pair & 63;
    int bt = bth >> 3, h = bth & 7;

    float M = -1e30f;
    #pragma unroll
    for (int s = 0; s < NSPLIT; s++)
        M = fmaxf(M, d_pm[(s*BTH + bth)*NLTN + i]);
    float L = 0.f, a0 = 0.f;
    #pragma unroll
    for (int s = 0; s < NSPLIT; s++){
        float ws = __expf(d_pm[(s*BTH + bth)*NLTN + i] - M);
        L += ws * d_pl[(s*BTH + bth)*NLTN + i];
        const float* po = d_po + (size_t)(s*BTH + bth)*NLTN*DHEAD + i*DHEAD;
        a0 += ws * po[half*32 + lane];
    }
    float invL = 1.f / L;
    float* ob = d_obuf + (size_t)(bt*NLTN + i)*DEMB + h*DHEAD;
    ob[half*32 + lane] = a0 * invL;
}

// ------------------------- launch -------------------------------------------
extern "C" void kernel_launch(void* const* d_in, const int* in_sizes, int n_in,
                              void* d_out, int out_size)
{
    const float* src = (const float*)d_in[0];
    const float* ltn = (const float*)d_in[1];
    const float* gs  = (const float*)d_in[2];
    const float* bs  = (const float*)d_in[3];
    const float* gl  = (const float*)d_in[4];
    const float* bl  = (const float*)d_in[5];
    const float* Wq  = (const float*)d_in[6];
    const float* Wkv = (const float*)d_in[7];
    const float* Wo  = (const float*)d_in[8];
    float* out = (float*)d_out;

    cudaFuncSetAttribute(kv_gemm,     cudaFuncAttributeMaxDynamicSharedMemorySize, KV_SMEM);
    cudaFuncSetAttribute(attn_kernel, cudaFuncAttributeMaxDynamicSharedMemorySize, ATT_SMEM);

    ln_kernel<<<NTOK/8 + 768, 256>>>(src, ltn, gs, bs, gl, bl, Wkv);
    kv_gemm<<<dim3(8, 524), 256, KV_SMEM>>>(Wq);
    attn_kernel<<<dim3(NSPLIT, BTH), 256, ATT_SMEM>>>();
    combine_kernel<<<1024, 256>>>();
    o_gemm<<<dim3(DIM/64, (BT*NLTN)/64), 256>>>(Wo, out);
}

// round 17
// speedup vs baseline: 1.1045x; 1.0053x over previous
#include <cuda_runtime.h>
#include <cstdint>
#include <math.h>

#define NSRC   8192
#define NLTN   64
#define NCTX   8256
#define BT     8
#define DIM    768
#define DEMB   512
#define HEADS  8
#define DHEAD  64
#define NTOK   (BT*NCTX)      // 66048
#define NSPLIT 43
#define SPLEN  192            // NCTX / NSPLIT (exact)
#define NCH    6              // SPLEN / 32 (exact)
#define BTH    (BT*HEADS)     // 64
#define QSCALE 0.18033688011112042f   // 0.125 * log2(e)

// ------------------------- device scratch (no allocs allowed) ---------------
__device__ float d_ctxn[(size_t)NTOK*DIM];       // LayerNorm'd ctx (tf32-rounded)
__device__ float d_ltnn[BT*NLTN*DIM];            // compact ltn_n (full fp32)
__device__ float d_q   [BT*NLTN*DEMB];
__device__ float d_kv  [(size_t)NTOK*2*DEMB];    // k | v (tf32-rounded values)
__device__ float d_wt  [1024*DIM];               // Wkv^T, tf32-rounded
__device__ float d_po  [(size_t)NSPLIT*BTH*NLTN*DHEAD];
__device__ float d_pm  [NSPLIT*BTH*NLTN];        // base-2 log domain
__device__ float d_pl  [NSPLIT*BTH*NLTN];
__device__ float d_obuf[BT*NLTN*DEMB];

__device__ __forceinline__ unsigned f2tf(float x){
    unsigned r; asm("cvt.rna.tf32.f32 %0, %1;" : "=r"(r) : "f"(x)); return r;
}
__device__ __forceinline__ float tff(float x){ return __uint_as_float(f2tf(x)); }

__device__ __forceinline__ void mma_tf32(float* c, const unsigned* a, const unsigned* b){
    asm volatile(
        "mma.sync.aligned.m16n8k8.row.col.f32.tf32.tf32.f32 "
        "{%0,%1,%2,%3},{%4,%5,%6,%7},{%8,%9},{%0,%1,%2,%3};\n"
        : "+f"(c[0]), "+f"(c[1]), "+f"(c[2]), "+f"(c[3])
        : "r"(a[0]), "r"(a[1]), "r"(a[2]), "r"(a[3]), "r"(b[0]), "r"(b[1]));
}

__device__ __forceinline__ uint32_t smem_u32(const void* p){
    uint32_t a;
    asm("{ .reg .u64 t; cvta.to.shared.u64 t, %1; cvt.u32.u64 %0, t; }" : "=r"(a) : "l"(p));
    return a;
}

#define CP_ASYNC16(dst_u32, src_ptr) \
    asm volatile("cp.async.ca.shared.global [%0], [%1], 16;" :: "r"(dst_u32), "l"(src_ptr) : "memory")
#define CP_COMMIT() asm volatile("cp.async.commit_group;" ::: "memory")
#define CP_WAIT(N)  asm volatile("cp.async.wait_group %0;" :: "n"(N) : "memory")

// ------------------------- LayerNorm (+ fused Wkv transpose) ----------------
__global__ __launch_bounds__(256) void ln_kernel(
    const float* __restrict__ src, const float* __restrict__ ltn,
    const float* __restrict__ gs,  const float* __restrict__ bs,
    const float* __restrict__ gl,  const float* __restrict__ bl,
    const float* __restrict__ W)
{
    if (blockIdx.x >= NTOK/8){
        __shared__ float tile[32][33];
        int b2 = blockIdx.x - NTOK/8;
        int bx = (b2 & 31)*32;            // n base (0..1023)
        int by = (b2 >> 5)*32;            // k base (0..767)
        int x = threadIdx.x & 31, y = threadIdx.x >> 5;
        #pragma unroll
        for (int i = 0; i < 32; i += 8)
            tile[y+i][x] = W[(size_t)(by+y+i)*1024 + bx + x];
        __syncthreads();
        #pragma unroll
        for (int i = 0; i < 32; i += 8)
            d_wt[(size_t)(bx+y+i)*DIM + by + x] = tff(tile[x][y+i]);
        return;
    }

    int warp = blockIdx.x*8 + (threadIdx.x>>5);
    int lane = threadIdx.x & 31;
    int bt = warp / NCTX;
    int j  = warp % NCTX;
    const float *x, *g, *b;
    bool is_ltn = (j >= NSRC);
    if (!is_ltn){ x = src + (size_t)(bt*NSRC + j)*DIM;        g = gs; b = bs; }
    else        { x = ltn + (size_t)(bt*NLTN + (j-NSRC))*DIM; g = gl; b = bl; }

    float4 v[6];
    float s = 0.f, sq = 0.f;
    #pragma unroll
    for (int i = 0; i < 6; i++){
        v[i] = *(const float4*)(x + i*128 + lane*4);
        s  += v[i].x + v[i].y + v[i].z + v[i].w;
        sq += v[i].x*v[i].x + v[i].y*v[i].y + v[i].z*v[i].z + v[i].w*v[i].w;
    }
    #pragma unroll
    for (int o = 16; o > 0; o >>= 1){
        s  += __shfl_xor_sync(0xffffffffu, s,  o);
        sq += __shfl_xor_sync(0xffffffffu, sq, o);
    }
    float mu  = s * (1.f/DIM);
    float var = sq * (1.f/DIM) - mu*mu;
    float rs  = rsqrtf(var + 1e-5f);

    float* out  = d_ctxn + (size_t)warp*DIM;
    float* out2 = is_ltn ? (d_ltnn + (size_t)(bt*NLTN + (j-NSRC))*DIM) : 0;
    #pragma unroll
    for (int i = 0; i < 6; i++){
        int idx = i*128 + lane*4;
        float4 gv = *(const float4*)(g + idx);
        float4 bv = *(const float4*)(b + idx);
        float4 o4;
        o4.x = (v[i].x - mu)*rs*gv.x + bv.x;
        o4.y = (v[i].y - mu)*rs*gv.y + bv.y;
        o4.z = (v[i].z - mu)*rs*gv.z + bv.z;
        o4.w = (v[i].w - mu)*rs*gv.w + bv.w;
        if (is_ltn) *(float4*)(out2 + idx) = o4;     // full fp32 for Q path
        float4 r4;                                    // tf32-rounded for kv GEMM
        r4.x = tff(o4.x); r4.y = tff(o4.y); r4.z = tff(o4.z); r4.w = tff(o4.w);
        *(float4*)(out + idx) = r4;
    }
}

// ------------------------- generic small fp32 GEMM (64x64 tiles) ------------
__device__ __forceinline__ void gemm64_dyn(
    const float* __restrict__ A, const float* __restrict__ B, float* __restrict__ C,
    int N, int K, int m0, int n0, float* As /*16x68*/, float* Bs /*16x68*/)
{
    int t = threadIdx.x;
    int ar = t>>2, ak = (t&3)*4;
    int br = t>>4, bc = (t&15)*4;
    int ty = t>>4, tx = t&15;
    float acc[4][4];
    #pragma unroll
    for (int i=0;i<4;i++) for (int j=0;j<4;j++) acc[i][j]=0.f;

    for (int kc = 0; kc < K; kc += 16){
        float4 av = *(const float4*)(A + (size_t)(m0+ar)*K + kc + ak);
        float4 bv = *(const float4*)(B + (size_t)(kc+br)*N + n0 + bc);
        __syncthreads();
        As[(ak+0)*68+ar]=av.x; As[(ak+1)*68+ar]=av.y; As[(ak+2)*68+ar]=av.z; As[(ak+3)*68+ar]=av.w;
        Bs[br*68+bc+0]=bv.x; Bs[br*68+bc+1]=bv.y; Bs[br*68+bc+2]=bv.z; Bs[br*68+bc+3]=bv.w;
        __syncthreads();
        #pragma unroll
        for (int k = 0; k < 16; k++){
            float a[4], b[4];
            #pragma unroll
            for (int i=0;i<4;i++) a[i] = As[k*68 + ty*4+i];
            #pragma unroll
            for (int j=0;j<4;j++) b[j] = Bs[k*68 + tx*4+j];
            #pragma unroll
            for (int i=0;i<4;i++)
                #pragma unroll
                for (int j=0;j<4;j++) acc[i][j] += a[i]*b[j];
        }
    }
    #pragma unroll
    for (int i=0;i<4;i++)
        #pragma unroll
        for (int j=0;j<4;j++)
            C[(size_t)(m0+ty*4+i)*N + n0+tx*4+j] = acc[i][j];
}

__global__ __launch_bounds__(256) void o_gemm(const float* __restrict__ Wo, float* __restrict__ out){
    __shared__ float As[16*68], Bs[16*68];
    gemm64_dyn(d_obuf, Wo, out, DIM, DEMB, blockIdx.y*64, blockIdx.x*64, As, Bs);
}

// ------------------------- KV GEMM (+ fused Q projection) -------------------
#define KV_NCHUNK 24
#define KV_SMEM   73728
#define AOFF(b)   ((b)*18432)
#define BOFF(b)   (36864 + (b)*18432)

__global__ __launch_bounds__(256,2) void kv_gemm(const float* __restrict__ Wq)
{
    extern __shared__ float smf[];
    uint32_t sb = smem_u32(smf);

    if (blockIdx.y >= 516){
        gemm64_dyn(d_ltnn, Wq, d_q, DEMB, DIM,
                   (blockIdx.y - 516)*64, blockIdx.x*64, smf, smf + 1088);
        return;
    }

    int t = threadIdx.x, lane = t & 31, w = t >> 5;
    int m0 = blockIdx.y*128, n0 = blockIdx.x*128;
    int g = lane >> 2, tg = lane & 3;
    int wm = (w >> 2)*64, wn = (w & 3)*32;

    float acc[4][4][4];
    #pragma unroll
    for (int a=0;a<4;a++) for (int b=0;b<4;b++) for (int c=0;c<4;c++) acc[a][b][c]=0.f;

    const float* Ag = d_ctxn + (size_t)m0*DIM;
    const float* Bg = d_wt   + (size_t)n0*DIM;

    #pragma unroll
    for (int i = 0; i < 4; i++){
        int f = t + i*256, r = f>>3, cl = (f&7)*4;
        CP_ASYNC16(sb + AOFF(0) + (r*36+cl)*4, Ag + (size_t)r*DIM + cl);
        CP_ASYNC16(sb + BOFF(0) + (r*36+cl)*4, Bg + (size_t)r*DIM + cl);
    }
    CP_COMMIT();

    for (int c = 0; c < KV_NCHUNK; c++){
        if (c + 1 < KV_NCHUNK){
            int nb = (c+1) & 1, kc = (c+1)*32;
            #pragma unroll
            for (int i = 0; i < 4; i++){
                int f = t + i*256, r = f>>3, cl = (f&7)*4;
                CP_ASYNC16(sb + AOFF(nb) + (r*36+cl)*4, Ag + (size_t)r*DIM + kc + cl);
                CP_ASYNC16(sb + BOFF(nb) + (r*36+cl)*4, Bg + (size_t)r*DIM + kc + cl);
            }
            CP_COMMIT();
            CP_WAIT(1);
        } else {
            CP_WAIT(0);
        }
        __syncthreads();

        const float* As = smf + AOFF(c&1)/4;
        const float* Bs = smf + BOFF(c&1)/4;
        #pragma unroll
        for (int ks = 0; ks < 4; ks++){
            int k0 = ks*8;
            unsigned af[4][4], bf[4][2];
            #pragma unroll
            for (int mi = 0; mi < 4; mi++){
                int mb = wm + mi*16;
                af[mi][0] = __float_as_uint(As[(mb+g  )*36 + k0+tg  ]);
                af[mi][1] = __float_as_uint(As[(mb+8+g)*36 + k0+tg  ]);
                af[mi][2] = __float_as_uint(As[(mb+g  )*36 + k0+tg+4]);
                af[mi][3] = __float_as_uint(As[(mb+8+g)*36 + k0+tg+4]);
            }
            #pragma unroll
            for (int ni = 0; ni < 4; ni++){
                int nb2 = wn + ni*8;
                bf[ni][0] = __float_as_uint(Bs[(nb2+g)*36 + k0+tg  ]);
                bf[ni][1] = __float_as_uint(Bs[(nb2+g)*36 + k0+tg+4]);
            }
            #pragma unroll
            for (int mi = 0; mi < 4; mi++)
                #pragma unroll
                for (int ni = 0; ni < 4; ni++)
                    mma_tf32(acc[mi][ni], af[mi], bf[ni]);
        }
        __syncthreads();
    }

    #pragma unroll
    for (int mi = 0; mi < 4; mi++){
        #pragma unroll
        for (int ni = 0; ni < 4; ni++){
            int r0 = m0 + wm + mi*16 + g;
            int cc = n0 + wn + ni*8 + 2*tg;
            *(float2*)(d_kv + (size_t)r0*1024 + cc)     = make_float2(tff(acc[mi][ni][0]), tff(acc[mi][ni][1]));
            *(float2*)(d_kv + (size_t)(r0+8)*1024 + cc) = make_float2(tff(acc[mi][ni][2]), tff(acc[mi][ni][3]));
        }
    }
}

// ------------------------- Flash attention, split-KV, tf32 mma --------------
// Base-2 softmax: Q pre-scaled by 0.125*log2(e); exp2f everywhere.
#define QS_O  0
#define KS_O  4352
#define VS_O  8704
#define SP_O  13312
#define ST_O  15616
#define ATT_SMEM 63232

__global__ __launch_bounds__(256) void attn_kernel()
{
    extern __shared__ float sm[];
    uint32_t sb = smem_u32(sm);
    unsigned* SPu = (unsigned*)(sm + SP_O);

    int split = blockIdx.x;
    int bth   = blockIdx.y;
    int bt = bth >> 3, h = bth & 7;
    int t = threadIdx.x, lane = t & 31, w = t >> 5;
    int g = lane >> 2, tg = lane & 3;

    {
        int i = t >> 2, dq = (t & 3)*16;
        const float* qp = d_q + (size_t)(bt*NLTN + i)*DEMB + h*DHEAD + dq;
        #pragma unroll
        for (int c = 0; c < 4; c++){
            float4 qv = *(const float4*)(qp + c*4);
            float4 r4;
            r4.x = tff(QSCALE*qv.x); r4.y = tff(QSCALE*qv.y);
            r4.z = tff(QSCALE*qv.z); r4.w = tff(QSCALE*qv.w);
            *(float4*)&sm[QS_O + i*68 + dq + c*4] = r4;
        }
    }
    if (t < 64){ sm[ST_O + t] = -1e30f; sm[ST_O + 64 + t] = 0.f; }

    int i0 = (w >> 1)*16;
    int j0 = (w & 1)*16;
    int d0 = (w & 1)*32;

    float oc[4][4];
    #pragma unroll
    for (int a=0;a<4;a++) for (int b=0;b<4;b++) oc[a][b]=0.f;

    int ldj = t & 31;
    int ldd = (t >> 5)*8;
    size_t tokbase = (size_t)(bt*NCTX + split*SPLEN);
    const float* kvbase = d_kv + (tokbase + ldj)*1024 + h*DHEAD + ldd;
    uint32_t Ksm = sb + (KS_O + ldj*68 + ldd)*4;
    uint32_t Vsm = sb + (VS_O + ldj*72 + ldd)*4;

    CP_ASYNC16(Ksm,      kvbase);
    CP_ASYNC16(Ksm + 16, kvbase + 4);
    CP_ASYNC16(Vsm,      kvbase + DEMB);
    CP_ASYNC16(Vsm + 16, kvbase + DEMB + 4);
    CP_COMMIT();

    for (int ch = 0; ch < NCH; ch++){
        int b = ch & 1;
        CP_WAIT(0);
        __syncthreads();                       // bar1: chunk ch ready; PV(ch-1) done

        if (ch + 1 < NCH){
            const float* kp = kvbase + (size_t)(ch+1)*32*1024;
            uint32_t Kd = Ksm + (b^1)*(2176*4);
            uint32_t Vd = Vsm + (b^1)*(2304*4);
            CP_ASYNC16(Kd,      kp);
            CP_ASYNC16(Kd + 16, kp + 4);
            CP_ASYNC16(Vd,      kp + DEMB);
            CP_ASYNC16(Vd + 16, kp + DEMB + 4);
            CP_COMMIT();
        }

        const float* Ksb = sm + KS_O + b*2176;
        const float* Vsb = sm + VS_O + b*2304;

        {
            float sc[2][4];
            #pragma unroll
            for (int ni=0;ni<2;ni++) for (int c=0;c<4;c++) sc[ni][c]=0.f;
            #pragma unroll
            for (int ks = 0; ks < 8; ks++){
                int k0 = ks*8;
                unsigned af[4], bf[2][2];
                af[0] = __float_as_uint(sm[QS_O + (i0+g  )*68 + k0+tg  ]);
                af[1] = __float_as_uint(sm[QS_O + (i0+8+g)*68 + k0+tg  ]);
                af[2] = __float_as_uint(sm[QS_O + (i0+g  )*68 + k0+tg+4]);
                af[3] = __float_as_uint(sm[QS_O + (i0+8+g)*68 + k0+tg+4]);
                #pragma unroll
                for (int ni = 0; ni < 2; ni++){
                    bf[ni][0] = __float_as_uint(Ksb[(j0+ni*8+g)*68 + k0+tg  ]);
                    bf[ni][1] = __float_as_uint(Ksb[(j0+ni*8+g)*68 + k0+tg+4]);
                }
                #pragma unroll
                for (int ni = 0; ni < 2; ni++) mma_tf32(sc[ni], af, bf[ni]);
            }
            #pragma unroll
            for (int ni = 0; ni < 2; ni++){
                int jc = j0 + ni*8 + 2*tg;
                SPu[(jc  )*72 + i0+g  ] = __float_as_uint(sc[ni][0]);
                SPu[(jc+1)*72 + i0+g  ] = __float_as_uint(sc[ni][1]);
                SPu[(jc  )*72 + i0+8+g] = __float_as_uint(sc[ni][2]);
                SPu[(jc+1)*72 + i0+8+g] = __float_as_uint(sc[ni][3]);
            }
        }
        __syncthreads();                       // bar2

        {
            int r  = w*8 + (lane>>2);
            int qt = lane & 3;
            float sv[8];
            float mx = -1e30f;
            #pragma unroll
            for (int c = 0; c < 8; c++){
                int j = qt + 4*c;
                float s = __uint_as_float(SPu[j*72 + r]);
                sv[c] = s;
                mx = fmaxf(mx, s);
            }
            mx = fmaxf(mx, __shfl_xor_sync(0xffffffffu, mx, 1));
            mx = fmaxf(mx, __shfl_xor_sync(0xffffffffu, mx, 2));
            float oldm = sm[ST_O + r];
            float newm = fmaxf(oldm, mx);
            float psum = 0.f;
            #pragma unroll
            for (int c = 0; c < 8; c++){
                float p = exp2f(sv[c] - newm);
                psum += p;
                SPu[(qt + 4*c)*72 + r] = f2tf(p);
            }
            psum += __shfl_xor_sync(0xffffffffu, psum, 1);
            psum += __shfl_xor_sync(0xffffffffu, psum, 2);
            if (qt == 0){
                float f = exp2f(oldm - newm);
                sm[ST_O + 64 + r] = sm[ST_O + 64 + r]*f + psum;
                sm[ST_O + r]       = newm;
                sm[ST_O + 128 + r] = f;
            }
        }
        __syncthreads();                       // bar3

        {
            float f1 = sm[ST_O + 128 + i0+g], f2 = sm[ST_O + 128 + i0+8+g];
            #pragma unroll
            for (int ni = 0; ni < 4; ni++){
                oc[ni][0]*=f1; oc[ni][1]*=f1; oc[ni][2]*=f2; oc[ni][3]*=f2;
            }
            #pragma unroll
            for (int ks = 0; ks < 4; ks++){
                int k0 = ks*8;
                unsigned af[4], bf[4][2];
                af[0] = SPu[(k0+tg  )*72 + i0+g  ];
                af[1] = SPu[(k0+tg  )*72 + i0+8+g];
                af[2] = SPu[(k0+tg+4)*72 + i0+g  ];
                af[3] = SPu[(k0+tg+4)*72 + i0+8+g];
                #pragma unroll
                for (int ni = 0; ni < 4; ni++){
                    bf[ni][0] = __float_as_uint(Vsb[(k0+tg  )*72 + d0+ni*8+g]);
                    bf[ni][1] = __float_as_uint(Vsb[(k0+tg+4)*72 + d0+ni*8+g]);
                }
                #pragma unroll
                for (int ni = 0; ni < 4; ni++) mma_tf32(oc[ni], af, bf[ni]);
            }
        }
    }

    __syncthreads();
    {
        float* po = d_po + (size_t)(split*BTH + bth)*NLTN*DHEAD;
        #pragma unroll
        for (int ni = 0; ni < 4; ni++){
            int cc = d0 + ni*8 + 2*tg;
            *(float2*)(po + (i0+g)*DHEAD + cc)   = make_float2(oc[ni][0], oc[ni][1]);
            *(float2*)(po + (i0+8+g)*DHEAD + cc) = make_float2(oc[ni][2], oc[ni][3]);
        }
        if (t < 64){
            d_pm[(split*BTH + bth)*NLTN + t] = sm[ST_O + t];
            d_pl[(split*BTH + bth)*NLTN + t] = sm[ST_O + 64 + t];
        }
    }
}

// ------------------------- combine splits (R14 form, base-2) ----------------
__global__ __launch_bounds__(256) void combine_kernel()
{
    int gw = blockIdx.x*8 + (threadIdx.x>>5);   // 0..4095
    int lane = threadIdx.x & 31;
    int bth = gw >> 6, i = gw & 63;
    int bt = bth >> 3, h = bth & 7;

    float M = -1e30f;
    #pragma unroll
    for (int s = 0; s < NSPLIT; s++)
        M = fmaxf(M, d_pm[(s*BTH + bth)*NLTN + i]);
    float L = 0.f, a0 = 0.f, a1 = 0.f;
    #pragma unroll
    for (int s = 0; s < NSPLIT; s++){
        float ws = exp2f(d_pm[(s*BTH + bth)*NLTN + i] - M);
        L += ws * d_pl[(s*BTH + bth)*NLTN + i];
        const float* po = d_po + (size_t)(s*BTH + bth)*NLTN*DHEAD + i*DHEAD;
        a0 += ws * po[lane];
        a1 += ws * po[lane+32];
    }
    float invL = 1.f / L;
    float* ob = d_obuf + (size_t)(bt*NLTN + i)*DEMB + h*DHEAD;
    ob[lane]    = a0 * invL;
    ob[lane+32] = a1 * invL;
}

// ------------------------- launch -------------------------------------------
extern "C" void kernel_launch(void* const* d_in, const int* in_sizes, int n_in,
                              void* d_out, int out_size)
{
    const float* src = (const float*)d_in[0];
    const float* ltn = (const float*)d_in[1];
    const float* gs  = (const float*)d_in[2];
    const float* bs  = (const float*)d_in[3];
    const float* gl  = (const float*)d_in[4];
    const float* bl  = (const float*)d_in[5];
    const float* Wq  = (const float*)d_in[6];
    const float* Wkv = (const float*)d_in[7];
    const float* Wo  = (const float*)d_in[8];
    float* out = (float*)d_out;

    cudaFuncSetAttribute(kv_gemm,     cudaFuncAttributeMaxDynamicSharedMemorySize, KV_SMEM);
    cudaFuncSetAttribute(attn_kernel, cudaFuncAttributeMaxDynamicSharedMemorySize, ATT_SMEM);

    ln_kernel<<<NTOK/8 + 768, 256>>>(src, ltn, gs, bs, gl, bl, Wkv);
    kv_gemm<<<dim3(8, 524), 256, KV_SMEM>>>(Wq);
    attn_kernel<<<dim3(NSPLIT, BTH), 256, ATT_SMEM>>>();
    combine_kernel<<<512, 256>>>();
    o_gemm<<<dim3(DIM/64, (BT*NLTN)/64), 256>>>(Wo, out);
}